// round 5
// baseline (speedup 1.0000x reference)
#include <cuda_runtime.h>

#define Nn 128
#define Tn 2048
#define Bn 64

// Precomputed exp-domain constants (written by prep_kernel each launch).
__device__ __align__(16) float g_ET[Nn * Nn];   // ET[j*N + i] = forbidden ? 0 : exp(trans[i][j])
__device__ float g_stexp[Nn];                   // exp(start) or 0
__device__ float g_enexp[Nn];                   // exp(end) or 0

__global__ void prep_kernel(const float* __restrict__ trans,
                            const float* __restrict__ st,
                            const float* __restrict__ en,
                            const int* __restrict__ ftr,
                            const int* __restrict__ fst,
                            const int* __restrict__ fen,
                            float* __restrict__ out)
{
    int idx = blockIdx.x * blockDim.x + threadIdx.x;
    if (idx < Nn * Nn) {
        int j = idx >> 7;
        int i = idx & (Nn - 1);
        g_ET[idx] = ftr[i * Nn + j] ? 0.0f : expf(trans[i * Nn + j]);
    }
    if (idx < Nn) {
        g_stexp[idx] = fst[idx] ? 0.0f : expf(st[idx]);
        g_enexp[idx] = fen[idx] ? 0.0f : expf(en[idx]);
    }
    if (idx < Bn) out[idx] = 0.0f;
}

// Packed fp32x2 ops (Blackwell): 2 fp32 FMAs/ADDs per instruction on the fma pipe.
__device__ __forceinline__ unsigned long long ffma2(unsigned long long a,
                                                    unsigned long long b,
                                                    unsigned long long c)
{
    unsigned long long d;
    asm("fma.rn.f32x2 %0, %1, %2, %3;" : "=l"(d) : "l"(a), "l"(b), "l"(c));
    return d;
}

__device__ __forceinline__ unsigned long long addf2(unsigned long long a,
                                                    unsigned long long b)
{
    unsigned long long d;
    asm("add.rn.f32x2 %0, %1, %2;" : "=l"(d) : "l"(a), "l"(b));
    return d;
}

__device__ __forceinline__ float unpack_add(unsigned long long a)
{
    float lo, hi;
    asm("mov.b64 {%0, %1}, %2;" : "=f"(lo), "=f"(hi) : "l"(a));
    return lo + hi;
}

// One CRF step. Each thread: 4 output columns (j = 4g..4g+3) x 32-row quarter (q).
// MODE: 0 = plain, 1 = apply pending renorm scale, 2 = compute new block max.
// U chunk order rotated by 2q so the 4 q-groups hit disjoint 16B chunks: conflict-free.
#define STEP(TSTEP, EMV, TGV, RB, WB, MODE)                                       \
    {                                                                             \
        const float4 emc = EMV;                                                   \
        const int4 tgc = TGV;                                                     \
        const int tp = (TSTEP) + 4;                                               \
        if (tp < Tn) {                                                            \
            EMV = *(const float4*)(emrow + tp * Nn);                              \
            TGV = *(const int4*)(tgrow + tp * Nn);                                \
        }                                                                         \
        float p0 = __expf(emc.x), p1 = __expf(emc.y);                             \
        float p2 = __expf(emc.z), p3 = __expf(emc.w);                             \
        if (sup) {                                                                \
            if (tgc.x == 0) p0 = 0.0f;                                            \
            if (tgc.y == 0) p1 = 0.0f;                                            \
            if (tgc.z == 0) p2 = 0.0f;                                            \
            if (tgc.w == 0) p3 = 0.0f;                                            \
        }                                                                         \
        const char* ub = (const char*)(U[RB]) + qbase;                            \
        unsigned long long a0 = 0ull, a1 = 0ull, a2 = 0ull, a3 = 0ull;            \
        unsigned long long a4 = 0ull, a5 = 0ull, a6 = 0ull, a7 = 0ull;            \
        _Pragma("unroll")                                                         \
        for (int k = 0; k < 8; k++) {                                             \
            ulonglong2 uk = *(const ulonglong2*)(ub + ((unsigned)((k + qrot) & 7) << 4)); \
            a0 = ffma2(Ep0[k].x, uk.x, a0);                                       \
            a1 = ffma2(Ep0[k].y, uk.y, a1);                                       \
            a2 = ffma2(Ep1[k].x, uk.x, a2);                                       \
            a3 = ffma2(Ep1[k].y, uk.y, a3);                                       \
            a4 = ffma2(Ep2[k].x, uk.x, a4);                                       \
            a5 = ffma2(Ep2[k].y, uk.y, a5);                                       \
            a6 = ffma2(Ep3[k].x, uk.x, a6);                                       \
            a7 = ffma2(Ep3[k].y, uk.y, a7);                                       \
        }                                                                         \
        float s0 = unpack_add(addf2(a0, a1));                                     \
        float s1 = unpack_add(addf2(a2, a3));                                     \
        float s2 = unpack_add(addf2(a4, a5));                                     \
        float s3 = unpack_add(addf2(a6, a7));                                     \
        s0 += __shfl_xor_sync(0xffffffffu, s0, 8);                                \
        s1 += __shfl_xor_sync(0xffffffffu, s1, 8);                                \
        s2 += __shfl_xor_sync(0xffffffffu, s2, 8);                                \
        s3 += __shfl_xor_sync(0xffffffffu, s3, 8);                                \
        s0 += __shfl_xor_sync(0xffffffffu, s0, 16);                               \
        s1 += __shfl_xor_sync(0xffffffffu, s1, 16);                               \
        s2 += __shfl_xor_sync(0xffffffffu, s2, 16);                               \
        s3 += __shfl_xor_sync(0xffffffffu, s3, 16);                               \
        if ((MODE) == 1) {                                                        \
            v0 = s0 * p0 * inv_pend; v1 = s1 * p1 * inv_pend;                     \
            v2 = s2 * p2 * inv_pend; v3 = s3 * p3 * inv_pend;                     \
            Sexp += e_pend;                                                       \
        } else {                                                                  \
            v0 = s0 * p0; v1 = s1 * p1; v2 = s2 * p2; v3 = s3 * p3;               \
        }                                                                         \
        if (q == 0) *(float4*)(U[WB] + (g << 2)) = make_float4(v0, v1, v2, v3);   \
        if ((MODE) == 2) {                                                        \
            unsigned int um = max(max(__float_as_uint(v0), __float_as_uint(v1)),  \
                                  max(__float_as_uint(v2), __float_as_uint(v3))); \
            unsigned int wmu = __reduce_max_sync(0xffffffffu, um);                \
            if (lane == 0) wmaxbuf[warp] = wmu;                                   \
        }                                                                         \
        __syncthreads();                                                          \
        if ((MODE) == 2) {                                                        \
            unsigned int rm = max(max(wmaxbuf[0], wmaxbuf[1]),                    \
                                  max(wmaxbuf[2], wmaxbuf[3]));                   \
            e_pend = (int)(rm >> 23) - 127;                                       \
            inv_pend = __int_as_float((127 - e_pend) << 23);                      \
        }                                                                         \
        if ((TSTEP) == Lm1) goto finalize;                                        \
    }

__global__ void __launch_bounds__(128, 1)
crf_kernel(const float* __restrict__ em,
           const int* __restrict__ mask,
           const int* __restrict__ tgt,
           float* __restrict__ out)
{
    __shared__ __align__(16) float U[2][Nn];   // scaled exp(alpha), double-buffered
    __shared__ unsigned int wmaxbuf[4];        // per-warp maxes (float-as-uint)
    __shared__ float zpart[4];
    __shared__ int s_len;

    const int tid = threadIdx.x;
    const int bidx = blockIdx.x;        // 128 blocks: (channel, batch)
    const int c = bidx & 1;             // 0 = supervised, 1 = partition
    const int b = bidx >> 1;
    const int warp = tid >> 5;
    const int lane = tid & 31;
    const int q = lane >> 3;            // quarter of the i-range (32 rows)
    const int gl = lane & 7;
    const int g = (warp << 3) + gl;     // column group: owns j = 4g..4g+3
    const bool sup = (c == 0);
    const unsigned int qbase = (unsigned)q << 7;   // byte offset of this quarter
    const int qrot = q << 1;                       // chunk rotation (anti-conflict)

    // ---- sequence length from mask (int32 bools) ----
    if (tid == 0) s_len = 0;
    __syncthreads();
    {
        int cnt = 0;
        const int* mrow = mask + b * Tn;
        for (int k = tid; k < Tn; k += 128) cnt += (mrow[k] != 0) ? 1 : 0;
        #pragma unroll
        for (int o = 16; o; o >>= 1) cnt += __shfl_xor_sync(0xffffffffu, cnt, o);
        if (lane == 0) atomicAdd(&s_len, cnt);
    }

    // ---- E registers: 4 columns x 32-row quarter, pre-rotated to match STEP ----
    ulonglong2 Ep0[8], Ep1[8], Ep2[8], Ep3[8];
    {
        const ulonglong2* e0 = (const ulonglong2*)(g_ET + (4 * g + 0) * Nn + (q << 5));
        const ulonglong2* e1 = (const ulonglong2*)(g_ET + (4 * g + 1) * Nn + (q << 5));
        const ulonglong2* e2 = (const ulonglong2*)(g_ET + (4 * g + 2) * Nn + (q << 5));
        const ulonglong2* e3 = (const ulonglong2*)(g_ET + (4 * g + 3) * Nn + (q << 5));
        #pragma unroll
        for (int k = 0; k < 8; k++) {
            const int kk = (k + qrot) & 7;
            Ep0[k] = e0[kk];
            Ep1[k] = e1[kk];
            Ep2[k] = e2[kk];
            Ep3[k] = e3[kk];
        }
    }

    const float* emrow = em + (b * Tn) * Nn + (g << 2);
    const int*   tgrow = tgt + (b * Tn) * Nn + (g << 2);

    __syncthreads();
    int L = s_len;
    int Lm1 = L - 1;
    if (Lm1 < 0) Lm1 = 0;
    if (Lm1 > Tn - 1) Lm1 = Tn - 1;

    float v0, v1, v2, v3;
    int Sexp = 0;
    int e_pend = 0;
    float inv_pend = 1.0f;

    // ---- t = 0: alpha0 = emissions(0) + start; write U[0]; first block max ----
    {
        float4 em0v = *(const float4*)(emrow);
        int4 tg0v = *(const int4*)(tgrow);
        float4 st4 = *(const float4*)(g_stexp + (g << 2));
        float p0 = __expf(em0v.x), p1 = __expf(em0v.y);
        float p2 = __expf(em0v.z), p3 = __expf(em0v.w);
        if (sup) {
            if (tg0v.x == 0) p0 = 0.0f;
            if (tg0v.y == 0) p1 = 0.0f;
            if (tg0v.z == 0) p2 = 0.0f;
            if (tg0v.w == 0) p3 = 0.0f;
        }
        v0 = p0 * st4.x; v1 = p1 * st4.y; v2 = p2 * st4.z; v3 = p3 * st4.w;
        if (q == 0) *(float4*)(U[0] + (g << 2)) = make_float4(v0, v1, v2, v3);
        unsigned int um = max(max(__float_as_uint(v0), __float_as_uint(v1)),
                              max(__float_as_uint(v2), __float_as_uint(v3)));
        unsigned int wmu = __reduce_max_sync(0xffffffffu, um);
        if (lane == 0) wmaxbuf[warp] = wmu;
        __syncthreads();
        unsigned int rm = max(max(wmaxbuf[0], wmaxbuf[1]),
                              max(wmaxbuf[2], wmaxbuf[3]));
        e_pend = (int)(rm >> 23) - 127;
        inv_pend = __int_as_float((127 - e_pend) << 23);
    }
    if (Lm1 == 0) goto finalize;

    // ---- main scan: 4-step unroll, renorm once per 4 steps ----
    {
        float4 em0, em1, em2, em3;
        int4 tg0, tg1, tg2, tg3;
        em0 = *(const float4*)(emrow + 1 * Nn); tg0 = *(const int4*)(tgrow + 1 * Nn);
        em1 = *(const float4*)(emrow + 2 * Nn); tg1 = *(const int4*)(tgrow + 2 * Nn);
        em2 = *(const float4*)(emrow + 3 * Nn); tg2 = *(const int4*)(tgrow + 3 * Nn);
        em3 = *(const float4*)(emrow + 4 * Nn); tg3 = *(const int4*)(tgrow + 4 * Nn);

        for (int base = 1; base < Tn; base += 4) {
            STEP(base + 0, em0, tg0, 0, 1, 1)
            STEP(base + 1, em1, tg1, 1, 0, 0)
            STEP(base + 2, em2, tg2, 0, 1, 0)
            STEP(base + 3, em3, tg3, 1, 0, 2)
        }
    }

finalize:
    // z = Sexp*ln2 + log(sum_j v_j * exp(end_j));  loss = z1 - z0
    {
        float contrib = 0.0f;
        if (q == 0) {
            float4 en4 = *(const float4*)(g_enexp + (g << 2));
            contrib = v0 * en4.x + v1 * en4.y + v2 * en4.z + v3 * en4.w;
        }
        #pragma unroll
        for (int o = 16; o; o >>= 1) contrib += __shfl_xor_sync(0xffffffffu, contrib, o);
        if (lane == 0) zpart[warp] = contrib;
        __syncthreads();
        if (tid == 0) {
            float zs = (zpart[0] + zpart[1]) + (zpart[2] + zpart[3]);
            double z = (double)Sexp * 0.6931471805599453 + (double)logf(zs);
            float add = (float)(sup ? -z : z);
            atomicAdd(out + b, add);   // exactly 2 adds per b: commutative -> deterministic
        }
    }
}

#undef STEP

extern "C" void kernel_launch(void* const* d_in, const int* in_sizes, int n_in,
                              void* d_out, int out_size)
{
    const float* em    = (const float*)d_in[0];
    const int*   mask  = (const int*)d_in[1];
    const int*   tgt   = (const int*)d_in[2];
    const float* trans = (const float*)d_in[3];
    const float* st    = (const float*)d_in[4];
    const float* en    = (const float*)d_in[5];
    const int*   ftr   = (const int*)d_in[6];
    const int*   fst   = (const int*)d_in[7];
    const int*   fen   = (const int*)d_in[8];
    float* out = (float*)d_out;

    prep_kernel<<<64, 256>>>(trans, st, en, ftr, fst, fen, out);
    crf_kernel<<<2 * Bn, 128>>>(em, mask, tgt, out);
}